// round 7
// baseline (speedup 1.0000x reference)
#include <cuda_runtime.h>
#include <cuda_fp16.h>
#include <cstdint>

#define VOCAB 100000
#define EMBED 128
#define ROWS  12800   // 64*200
#define K_ITEMS 50
#define K_PAD 56      // ids padded to 56 (pad -> id 0 -> zero WT row)

#define N_CHUNKS 4    // 4 chunks of 32 embed dims
#define VT 160        // v per transpose tile
#define F4T 40        // float4 per e-row per transpose tile
#define ET 32         // e per transpose tile == chunk width
#define T_TILES 625   // VOCAB / VT, per chunk
#define G_RPB 8       // rows per gather item
#define G_TILES (ROWS / G_RPB)   // 1600 per chunk

#define NBLOCKS 148
#define NTHREADS 256
#define TOTAL_ITEMS (4 * T_TILES + 4 * G_TILES)   // 2500 + 6400 = 8900

// 25.6 MB scratch: WT[V][128] fp16, row 0 zeroed (id==0 masked).
__device__ __align__(256) __half g_WT[(size_t)VOCAB * EMBED];

// Work-queue state. Zero-initialized at load; self-reset by the last block
// each launch, so every call (and every graph replay) sees identical state.
__device__ int g_q;
__device__ int g_ready[N_CHUNKS];
__device__ int g_done;

__device__ __forceinline__ int ld_acquire(const int* p) {
    int v;
    asm volatile("ld.acquire.gpu.b32 %0, [%1];" : "=r"(v) : "l"(p));
    return v;
}

__device__ __forceinline__ int swz(int v, int e) {
    return v * 32 + ((e + v + (v >> 2)) & 31);
}

union Smem {
    float ts[VT * 32];                 // 20 KB transpose staging
    int   ids[G_RPB][K_PAD];           // gather id staging
};

__global__ __launch_bounds__(NTHREADS) void fused(
    const float4* __restrict__ W4,     // W [128, 100000] fp32
    const int*    __restrict__ ids,    // [ROWS, 50]
    const float*  __restrict__ bias,   // [128]
    float*        __restrict__ out)    // [ROWS, 128]
{
    __shared__ Smem sm;
    __shared__ int s_pos;

    const int tid = threadIdx.x;

    for (;;) {
        if (tid == 0) s_pos = atomicAdd(&g_q, 1);
        __syncthreads();
        const int pos = s_pos;
        if (pos >= TOTAL_ITEMS) break;

        // Schedule order: T0 T1 G0 T2 G1 T3 G2 G3  (T(c) strictly before G(c))
        int isT, chunk, tile;
        if      (pos < 625)  { isT = 1; chunk = 0; tile = pos; }
        else if (pos < 1250) { isT = 1; chunk = 1; tile = pos - 625; }
        else if (pos < 2850) { isT = 0; chunk = 0; tile = pos - 1250; }
        else if (pos < 3475) { isT = 1; chunk = 2; tile = pos - 2850; }
        else if (pos < 5075) { isT = 0; chunk = 1; tile = pos - 3475; }
        else if (pos < 5700) { isT = 1; chunk = 3; tile = pos - 5075; }
        else if (pos < 7300) { isT = 0; chunk = 2; tile = pos - 5700; }
        else                 { isT = 0; chunk = 3; tile = pos - 7300; }

        if (isT) {
            // ---- Transpose tile: 32 E x 160 V, W fp32 -> WT fp16 ----
            const int vt4 = tile * F4T;
            const int vt  = tile * VT;
            const int et  = chunk * ET;

            #pragma unroll
            for (int i = 0; i < 5; i++) {
                const int idx = i * NTHREADS + tid;
                const int e = idx / F4T;
                const int c = idx % F4T;
                const float4 w = W4[(size_t)(et + e) * (VOCAB / 4) + vt4 + c];
                const int v = 4 * c;
                sm.ts[swz(v + 0, e)] = w.x;
                sm.ts[swz(v + 1, e)] = w.y;
                sm.ts[swz(v + 2, e)] = w.z;
                sm.ts[swz(v + 3, e)] = w.w;
            }
            __syncthreads();

            uint2* WT_u2 = (uint2*)g_WT;
            #pragma unroll
            for (int i = 0; i < 5; i++) {
                const int idx = i * NTHREADS + tid;
                const int v  = idx >> 3;
                const int e4 = idx & 7;
                const int e  = 4 * e4;
                __half2 h0 = __floats2half2_rn(sm.ts[swz(v, e + 0)], sm.ts[swz(v, e + 1)]);
                __half2 h1 = __floats2half2_rn(sm.ts[swz(v, e + 2)], sm.ts[swz(v, e + 3)]);
                uint2 o;
                o.x = *reinterpret_cast<unsigned int*>(&h0);
                o.y = *reinterpret_cast<unsigned int*>(&h1);
                if (vt + v == 0) { o.x = 0u; o.y = 0u; }   // mask column 0
                WT_u2[(size_t)(vt + v) * (EMBED / 4) + (et >> 2) + e4] = o;
            }
            __syncthreads();
            if (tid == 0) {
                __threadfence();
                atomicAdd(&g_ready[chunk], 1);   // release: tile visible
            }
        } else {
            // ---- Gather item: 8 rows x 32 dims of chunk `chunk` ----
            const int row0 = tile * G_RPB;

            #pragma unroll
            for (int i = tid; i < G_RPB * K_PAD; i += NTHREADS) {
                const int r = i / K_PAD, s = i % K_PAD;
                sm.ids[r][s] = (s < K_ITEMS)
                    ? __ldg(&ids[(size_t)(row0 + r) * K_ITEMS + s]) : 0;
            }
            if (tid == 0) {
                while (ld_acquire(&g_ready[chunk]) < T_TILES) __nanosleep(100);
            }
            __syncthreads();   // ids staged + chunk ready (acquire by tid0 + bar)

            const int lane = tid & 31;
            const int warp = tid >> 5;
            const int sub  = lane & 3;     // 4 lanes x 16B cover one 64B row-chunk
            const int grp  = lane >> 2;    // 8 ids in flight per warp iteration
            const int row  = row0 + warp;

            const __half* wbase = g_WT + (size_t)chunk * ET + sub * 8;
            const __half2 z = __float2half2_rn(0.f);
            __half2 h0 = z, h1 = z, h2 = z, h3 = z;

            #pragma unroll
            for (int it = 0; it < K_PAD / 8; it++) {     // 7 iterations
                const int v = sm.ids[warp][it * 8 + grp];
                const int4 r = __ldcg((const int4*)(wbase + (size_t)v * EMBED));
                h0 = __hadd2(h0, *reinterpret_cast<const __half2*>(&r.x));
                h1 = __hadd2(h1, *reinterpret_cast<const __half2*>(&r.y));
                h2 = __hadd2(h2, *reinterpret_cast<const __half2*>(&r.z));
                h3 = __hadd2(h3, *reinterpret_cast<const __half2*>(&r.w));
            }

            float f[8];
            { const float2 t0 = __half22float2(h0); f[0] = t0.x; f[1] = t0.y; }
            { const float2 t1 = __half22float2(h1); f[2] = t1.x; f[3] = t1.y; }
            { const float2 t2 = __half22float2(h2); f[4] = t2.x; f[5] = t2.y; }
            { const float2 t3 = __half22float2(h3); f[6] = t3.x; f[7] = t3.y; }

            #pragma unroll
            for (int m = 4; m <= 16; m <<= 1)
                #pragma unroll
                for (int i = 0; i < 8; i++)
                    f[i] += __shfl_xor_sync(0xffffffffu, f[i], m);

            if (grp == 0) {
                const float4 b0 = __ldg((const float4*)bias + chunk * 8 + sub * 2);
                const float4 b1 = __ldg((const float4*)bias + chunk * 8 + sub * 2 + 1);
                float4* o = (float4*)(out + (size_t)row * EMBED + chunk * ET + sub * 8);
                o[0] = make_float4(f[0] + b0.x, f[1] + b0.y, f[2] + b0.z, f[3] + b0.w);
                o[1] = make_float4(f[4] + b1.x, f[5] + b1.y, f[6] + b1.z, f[7] + b1.w);
            }
        }
        __syncthreads();   // smem reuse guard before next item
    }

    // Self-reset: the 148th block to exhaust the queue zeroes all state.
    // Every block only increments g_done AFTER finishing its last item, so
    // the resetter runs when no block will touch the queue/counters again.
    if (tid == 0) {
        __threadfence();
        if (atomicAdd(&g_done, 1) == NBLOCKS - 1) {
            g_q = 0;
            g_ready[0] = 0; g_ready[1] = 0; g_ready[2] = 0; g_ready[3] = 0;
            __threadfence();
            g_done = 0;
        }
    }
}

// ---------------------------------------------------------------------------
// Entry point. Inputs (metadata order): content_input int32, W f32, b f32.
// ---------------------------------------------------------------------------
extern "C" void kernel_launch(void* const* d_in, const int* in_sizes, int n_in,
                              void* d_out, int out_size) {
    const int*   ids = (const int*)d_in[0];
    const float* W   = (const float*)d_in[1];
    const float* b   = (const float*)d_in[2];
    float*       out = (float*)d_out;

    fused<<<NBLOCKS, NTHREADS>>>((const float4*)W, ids, b, out);
}

// round 8
// speedup vs baseline: 4.9220x; 4.9220x over previous
#include <cuda_runtime.h>
#include <cuda_fp16.h>
#include <cstdint>

#define VOCAB 100000
#define EMBED 128
#define ROWS  12800   // 64*200
#define K_ITEMS 50

// 25.6 MB scratch: transposed weights WT[V][E] in fp16. Row 0 is zeroed by
// the transpose so the gather needs no id!=0 mask.
__device__ __align__(256) __half g_WT[(size_t)VOCAB * EMBED];

// ---------------------------------------------------------------------------
// Kernel A: transpose W [E=128, V=100000] (fp32) -> WT [V, E] (fp16).
// Tile: 32 E x 160 V per block. float4 global loads, STS.128 smem stores
// with an f4-granularity XOR swizzle (slot = c ^ (e>>2)):
//   stores: lanes have consecutive c -> distinct banks mod 8 -> conflict-free
//   loads:  bank = 4*((v>>2)^e4) + (v&3); e4=0..7 x 4 aligned v -> 32 distinct
// Row v==0 of WT is written as zeros (multi-hot column 0 is masked out).
// ---------------------------------------------------------------------------
#define VT 160        // v per tile
#define F4T 40        // float4 per e-row per tile
#define ET 32         // e per tile

__global__ __launch_bounds__(256) void transpose_W(const float4* __restrict__ W4) {
    __shared__ float s[ET * VT];         // 20 KB, e-major, pitch 160 floats

    const int tid = threadIdx.x;
    const int vt4 = blockIdx.x * F4T;    // float4 offset along V
    const int vt  = blockIdx.x * VT;     // float offset along V
    const int et  = blockIdx.y * ET;     // float offset along E

    // ---- Read: 32 e-rows x 40 float4, 5 f4 per thread, vector STS ----
    #pragma unroll
    for (int i = 0; i < 5; i++) {
        const int idx = i * 256 + tid;
        const int e = idx / F4T;          // 0..31
        const int c = idx % F4T;          // 0..39
        const float4 w = W4[(size_t)(et + e) * (VOCAB / 4) + vt4 + c];
        float4* srow = (float4*)(s + e * VT);
        srow[c ^ (e >> 2)] = w;           // xor stays within 8-aligned block
    }
    __syncthreads();

    // ---- Write: 160 v-rows x 8 uint2 (4 halves each), 5 per thread ----
    uint2* WT_u2 = (uint2*)g_WT;          // 8 B = 4 halves per element
    #pragma unroll
    for (int i = 0; i < 5; i++) {
        const int idx = i * 256 + tid;
        const int v  = idx >> 3;          // 0..159
        const int e4 = idx & 7;           // 0..7 -> e = 4*e4 .. 4*e4+3
        const int base = 4 * ((v >> 2) ^ e4) + (v & 3);   // swizzled f4 slot
        const float f0 = s[(4 * e4 + 0) * VT + base];
        const float f1 = s[(4 * e4 + 1) * VT + base];
        const float f2 = s[(4 * e4 + 2) * VT + base];
        const float f3 = s[(4 * e4 + 3) * VT + base];
        __half2 h0 = __floats2half2_rn(f0, f1);
        __half2 h1 = __floats2half2_rn(f2, f3);
        uint2 o;
        o.x = *reinterpret_cast<unsigned int*>(&h0);
        o.y = *reinterpret_cast<unsigned int*>(&h1);
        if (vt + v == 0) { o.x = 0u; o.y = 0u; }   // mask column 0
        WT_u2[(size_t)(vt + v) * (EMBED / 4) + (et >> 2) + e4] = o;
    }
}

// ---------------------------------------------------------------------------
// Kernel B: embedding-bag gather from fp16 WT.
// 800 blocks x 256 thr = 6400 warps = one clean wave (43/SM, no tail).
// Each warp sequentially handles 2 rows. Per row: half-warp fetches one full
// 256 B WT row via LDG.128 (2 ids/iteration, 25 iters in 5 groups of 5);
// fp16 HADD2 accumulation within a group, fp32 across groups; shfl_xor(16)
// merges the half-warp partials. Branch-free (WT row 0 is zero).
// ---------------------------------------------------------------------------
#define ROWS_PER_BLOCK 16
#define THREADS_B 256

__global__ __launch_bounds__(THREADS_B) void gather_rows(
    const int* __restrict__ ids,         // [ROWS, 50] int32
    const float* __restrict__ bias,      // [128] fp32
    float* __restrict__ out)             // [ROWS, 128] fp32
{
    __shared__ int s_ids[ROWS_PER_BLOCK][K_ITEMS];

    const int tid  = threadIdx.x;
    const int lane = tid & 31;
    const int warp = tid >> 5;           // 0..7
    const int row0 = blockIdx.x * ROWS_PER_BLOCK;
    const int sub  = lane & 15;          // lane within half-warp
    const int half = lane >> 4;          // which id of the pair

    const int* gids = ids + (size_t)row0 * K_ITEMS;
    #pragma unroll
    for (int i = tid; i < ROWS_PER_BLOCK * K_ITEMS; i += THREADS_B) {
        s_ids[i / K_ITEMS][i % K_ITEMS] = gids[i];
    }
    __syncthreads();

    #pragma unroll
    for (int rr = 0; rr < 2; rr++) {
        const int lrow = 2 * warp + rr;      // 0..15
        const int row  = row0 + lrow;

        float a0 = 0.f, a1 = 0.f, a2 = 0.f, a3 = 0.f;
        float a4 = 0.f, a5 = 0.f, a6 = 0.f, a7 = 0.f;

        #pragma unroll
        for (int g = 0; g < 5; g++) {
            const __half2 z = __float2half2_rn(0.f);
            __half2 h0 = z, h1 = z, h2 = z, h3 = z;

            #pragma unroll
            for (int j = 0; j < 5; j++) {
                const int v = s_ids[lrow][10 * g + 2 * j + half];
                const int4 r = __ldcg((const int4*)(g_WT + (size_t)v * EMBED) + sub);
                h0 = __hadd2(h0, *reinterpret_cast<const __half2*>(&r.x));
                h1 = __hadd2(h1, *reinterpret_cast<const __half2*>(&r.y));
                h2 = __hadd2(h2, *reinterpret_cast<const __half2*>(&r.z));
                h3 = __hadd2(h3, *reinterpret_cast<const __half2*>(&r.w));
            }

            const float2 f0 = __half22float2(h0);
            const float2 f1 = __half22float2(h1);
            const float2 f2 = __half22float2(h2);
            const float2 f3 = __half22float2(h3);
            a0 += f0.x; a1 += f0.y; a2 += f1.x; a3 += f1.y;
            a4 += f2.x; a5 += f2.y; a6 += f3.x; a7 += f3.y;
        }

        // Merge the two half-warp partial sums (each covered different ids).
        a0 += __shfl_xor_sync(0xffffffffu, a0, 16);
        a1 += __shfl_xor_sync(0xffffffffu, a1, 16);
        a2 += __shfl_xor_sync(0xffffffffu, a2, 16);
        a3 += __shfl_xor_sync(0xffffffffu, a3, 16);
        a4 += __shfl_xor_sync(0xffffffffu, a4, 16);
        a5 += __shfl_xor_sync(0xffffffffu, a5, 16);
        a6 += __shfl_xor_sync(0xffffffffu, a6, 16);
        a7 += __shfl_xor_sync(0xffffffffu, a7, 16);

        // Lane writes float4 slot j = 2*sub + half (dims 8*sub + 4*half ..+3).
        const int j = 2 * sub + half;
        float4 o = (half == 0) ? make_float4(a0, a1, a2, a3)
                               : make_float4(a4, a5, a6, a7);
        const float4 bv = __ldg((const float4*)bias + j);
        o.x += bv.x; o.y += bv.y; o.z += bv.z; o.w += bv.w;
        ((float4*)(out + (size_t)row * EMBED))[j] = o;
    }
}

// ---------------------------------------------------------------------------
// Entry point. Inputs (metadata order): content_input int32, W f32, b f32.
// ---------------------------------------------------------------------------
extern "C" void kernel_launch(void* const* d_in, const int* in_sizes, int n_in,
                              void* d_out, int out_size) {
    const int*   ids = (const int*)d_in[0];
    const float* W   = (const float*)d_in[1];
    const float* b   = (const float*)d_in[2];
    float*       out = (float*)d_out;

    dim3 tgrid(VOCAB / VT, EMBED / ET);   // 625 x 4
    transpose_W<<<tgrid, 256>>>((const float4*)W);

    gather_rows<<<ROWS / ROWS_PER_BLOCK, THREADS_B>>>(ids, b, out);
}

// round 10
// speedup vs baseline: 5.2494x; 1.0665x over previous
#include <cuda_runtime.h>
#include <cuda_fp16.h>
#include <cstdint>

#define VOCAB 100000
#define EMBED 128
#define ROWS  12800   // 64*200
#define K_ITEMS 50

// 25.6 MB scratch: transposed weights WT[V][E] in fp16. Row 0 is zeroed by
// the transpose so the gather needs no id!=0 mask.
__device__ __align__(256) __half g_WT[(size_t)VOCAB * EMBED];

// ---------------------------------------------------------------------------
// Kernel A: transpose W [E=128, V=100000] (fp32) -> WT [V, E] (fp16).
// Tile: 32 E x 160 V per block. float4 global loads (LDG.cs: W is single-use
// streaming data -> evict-first, so it does NOT evict the 25.6 MB WT from L2;
// the gather then reads WT as pure L2 hits). STS.128 smem stores with an
// f4-granularity XOR swizzle (slot = c ^ (e>>2)); conflict-free both phases.
// Row v==0 of WT is written as zeros (multi-hot column 0 is masked out).
// ---------------------------------------------------------------------------
#define VT 160        // v per tile
#define F4T 40        // float4 per e-row per tile
#define ET 32         // e per tile

__global__ __launch_bounds__(256) void transpose_W(const float4* __restrict__ W4) {
    __shared__ float s[ET * VT];         // 20 KB, e-major, pitch 160 floats

    const int tid = threadIdx.x;
    const int vt4 = blockIdx.x * F4T;    // float4 offset along V
    const int vt  = blockIdx.x * VT;     // float offset along V
    const int et  = blockIdx.y * ET;     // float offset along E

    // ---- Read: 32 e-rows x 40 float4, 5 f4 per thread, vector STS ----
    #pragma unroll
    for (int i = 0; i < 5; i++) {
        const int idx = i * 256 + tid;
        const int e = idx / F4T;          // 0..31
        const int c = idx % F4T;          // 0..39
        const float4 w = __ldcs(&W4[(size_t)(et + e) * (VOCAB / 4) + vt4 + c]);
        float4* srow = (float4*)(s + e * VT);
        srow[c ^ (e >> 2)] = w;           // xor stays within 8-aligned block
    }
    __syncthreads();

    // ---- Write: 160 v-rows x 8 uint2 (4 halves each), 5 per thread ----
    uint2* WT_u2 = (uint2*)g_WT;          // 8 B = 4 halves per element
    #pragma unroll
    for (int i = 0; i < 5; i++) {
        const int idx = i * 256 + tid;
        const int v  = idx >> 3;          // 0..159
        const int e4 = idx & 7;           // 0..7 -> e = 4*e4 .. 4*e4+3
        const int base = 4 * ((v >> 2) ^ e4) + (v & 3);   // swizzled f4 slot
        const float f0 = s[(4 * e4 + 0) * VT + base];
        const float f1 = s[(4 * e4 + 1) * VT + base];
        const float f2 = s[(4 * e4 + 2) * VT + base];
        const float f3 = s[(4 * e4 + 3) * VT + base];
        __half2 h0 = __floats2half2_rn(f0, f1);
        __half2 h1 = __floats2half2_rn(f2, f3);
        uint2 o;
        o.x = *reinterpret_cast<unsigned int*>(&h0);
        o.y = *reinterpret_cast<unsigned int*>(&h1);
        if (vt + v == 0) { o.x = 0u; o.y = 0u; }   // mask column 0
        WT_u2[(size_t)(vt + v) * (EMBED / 4) + (et >> 2) + e4] = o;
    }
}

// ---------------------------------------------------------------------------
// Kernel B: embedding-bag gather from fp16 WT (exact R6 shape: measured best).
// 3200 blocks x 128 thr (4 rows/block, 1 warp/row). Each HALF-warp fetches
// one full 256 B WT row via LDG.128, so a warp consumes 2 ids/iteration ->
// 25 iterations in 5 groups of 5. fp16 HADD2 accumulation within a group,
// fp32 across groups. Branch-free (WT row 0 is zero). shfl_xor(16) merges
// the half-warp partials. Output stored with .cs (single-use, keep L2 for WT).
// ---------------------------------------------------------------------------
#define ROWS_PER_BLOCK 4
#define THREADS_B (ROWS_PER_BLOCK * 32)

__global__ __launch_bounds__(THREADS_B) void gather_rows(
    const int* __restrict__ ids,         // [ROWS, 50] int32
    const float* __restrict__ bias,      // [128] fp32
    float* __restrict__ out)             // [ROWS, 128] fp32
{
    __shared__ int s_ids[ROWS_PER_BLOCK][K_ITEMS];

    const int tid  = threadIdx.x;
    const int lane = tid & 31;
    const int wrow = tid >> 5;
    const int row0 = blockIdx.x * ROWS_PER_BLOCK;
    const int sub  = lane & 15;          // lane within half-warp
    const int half = lane >> 4;          // which id of the pair

    const int* gids = ids + (size_t)row0 * K_ITEMS;
    #pragma unroll
    for (int i = tid; i < ROWS_PER_BLOCK * K_ITEMS; i += THREADS_B) {
        s_ids[i / K_ITEMS][i % K_ITEMS] = gids[i];
    }
    __syncthreads();

    float a0 = 0.f, a1 = 0.f, a2 = 0.f, a3 = 0.f;
    float a4 = 0.f, a5 = 0.f, a6 = 0.f, a7 = 0.f;

    #pragma unroll
    for (int g = 0; g < 5; g++) {
        const __half2 z = __float2half2_rn(0.f);
        __half2 h0 = z, h1 = z, h2 = z, h3 = z;

        #pragma unroll
        for (int j = 0; j < 5; j++) {
            const int v = s_ids[wrow][10 * g + 2 * j + half];
            const int4 r = __ldg((const int4*)(g_WT + (size_t)v * EMBED) + sub);
            h0 = __hadd2(h0, *reinterpret_cast<const __half2*>(&r.x));
            h1 = __hadd2(h1, *reinterpret_cast<const __half2*>(&r.y));
            h2 = __hadd2(h2, *reinterpret_cast<const __half2*>(&r.z));
            h3 = __hadd2(h3, *reinterpret_cast<const __half2*>(&r.w));
        }

        const float2 f0 = __half22float2(h0);
        const float2 f1 = __half22float2(h1);
        const float2 f2 = __half22float2(h2);
        const float2 f3 = __half22float2(h3);
        a0 += f0.x; a1 += f0.y; a2 += f1.x; a3 += f1.y;
        a4 += f2.x; a5 += f2.y; a6 += f3.x; a7 += f3.y;
    }

    // Merge the two half-warp partial sums (each covered different ids).
    a0 += __shfl_xor_sync(0xffffffffu, a0, 16);
    a1 += __shfl_xor_sync(0xffffffffu, a1, 16);
    a2 += __shfl_xor_sync(0xffffffffu, a2, 16);
    a3 += __shfl_xor_sync(0xffffffffu, a3, 16);
    a4 += __shfl_xor_sync(0xffffffffu, a4, 16);
    a5 += __shfl_xor_sync(0xffffffffu, a5, 16);
    a6 += __shfl_xor_sync(0xffffffffu, a6, 16);
    a7 += __shfl_xor_sync(0xffffffffu, a7, 16);

    // Lane writes float4 slot j = 2*sub + half (dims 8*sub + 4*half ..+3).
    const int j = 2 * sub + half;
    float4 o = (half == 0) ? make_float4(a0, a1, a2, a3)
                           : make_float4(a4, a5, a6, a7);
    const float4 bv = __ldg((const float4*)bias + j);
    o.x += bv.x; o.y += bv.y; o.z += bv.z; o.w += bv.w;
    __stcs((float4*)(out + (size_t)(row0 + wrow) * EMBED) + j, o);
}

// ---------------------------------------------------------------------------
// Entry point. Inputs (metadata order): content_input int32, W f32, b f32.
// ---------------------------------------------------------------------------
extern "C" void kernel_launch(void* const* d_in, const int* in_sizes, int n_in,
                              void* d_out, int out_size) {
    const int*   ids = (const int*)d_in[0];
    const float* W   = (const float*)d_in[1];
    const float* b   = (const float*)d_in[2];
    float*       out = (float*)d_out;

    dim3 tgrid(VOCAB / VT, EMBED / ET);   // 625 x 4
    transpose_W<<<tgrid, 256>>>((const float4*)W);

    gather_rows<<<ROWS / ROWS_PER_BLOCK, THREADS_B>>>(ids, b, out);
}

// round 11
// speedup vs baseline: 5.2745x; 1.0048x over previous
#include <cuda_runtime.h>
#include <cuda_fp16.h>
#include <cstdint>

#define VOCAB 100000
#define EMBED 128
#define ROWS  12800   // 64*200
#define K_ITEMS 50

// 25.6 MB scratch: transposed weights WT[V][E] in fp16. Row 0 is zeroed by
// the transpose so the gather needs no id!=0 mask.
__device__ __align__(256) __half g_WT[(size_t)VOCAB * EMBED];

// ---------------------------------------------------------------------------
// Kernel A: transpose W [E=128, V=100000] (fp32) -> WT [V, E] (fp16).
// EXACT R6 version (measured best at 10.6us): float4 global loads, scalar
// smem stores with bank map idx(v,e) = v*32 + ((e + v + (v>>2)) & 31)
// (conflict-free for v-stride-4 stores, Δbank=5 coprime 32, and e-stride-4
// loads). Row v==0 of WT is written as zeros (multi-hot column 0 masked).
// ---------------------------------------------------------------------------
#define VT 160        // v per tile
#define F4T 40        // float4 per e-row per tile
#define ET 32         // e per tile

__device__ __forceinline__ int swz(int v, int e) {
    return v * 32 + ((e + v + (v >> 2)) & 31);
}

__global__ __launch_bounds__(256) void transpose_W(const float4* __restrict__ W4) {
    __shared__ float s[VT * 32];   // 20 KB

    const int tid = threadIdx.x;
    const int vt4 = blockIdx.x * F4T;    // float4 offset along V
    const int vt  = blockIdx.x * VT;     // float offset along V
    const int et  = blockIdx.y * ET;     // float offset along E

    #pragma unroll
    for (int i = 0; i < 5; i++) {
        const int idx = i * 256 + tid;
        const int e = idx / F4T;          // 0..31
        const int c = idx % F4T;          // 0..39
        const float4 w = W4[(size_t)(et + e) * (VOCAB / 4) + vt4 + c];
        const int v = 4 * c;
        s[swz(v + 0, e)] = w.x;
        s[swz(v + 1, e)] = w.y;
        s[swz(v + 2, e)] = w.z;
        s[swz(v + 3, e)] = w.w;
    }
    __syncthreads();

    uint2* WT_u2 = (uint2*)g_WT;          // 8 B = 4 halves per element
    #pragma unroll
    for (int i = 0; i < 5; i++) {
        const int idx = i * 256 + tid;
        const int v  = idx >> 3;          // 0..159
        const int e4 = idx & 7;           // 0..7
        const int e  = 4 * e4;
        __half2 h0 = __floats2half2_rn(s[swz(v, e + 0)], s[swz(v, e + 1)]);
        __half2 h1 = __floats2half2_rn(s[swz(v, e + 2)], s[swz(v, e + 3)]);
        uint2 o;
        o.x = *reinterpret_cast<unsigned int*>(&h0);
        o.y = *reinterpret_cast<unsigned int*>(&h1);
        if (vt + v == 0) { o.x = 0u; o.y = 0u; }   // mask column 0
        WT_u2[(size_t)(vt + v) * (EMBED / 4) + (et >> 2) + e4] = o;
    }
}

// ---------------------------------------------------------------------------
// Kernel B: embedding-bag gather from fp16 WT.
// 3200 blocks x 128 thr (4 rows/block, 1 warp/row). Each HALF-warp fetches
// one full 256 B WT row via LDG.128 (2 ids/iteration, 25 iterations).
// Accumulation is fp16 throughout, split across EVEN/ODD accumulator sets
// (chain length ~13 each) and converted to fp32 exactly once at the end —
// removes the per-group fp32 flushes and frees registers so ptxas can
// front-batch more independent loads. Branch-free (WT row 0 is zero).
// shfl_xor(16) merges the half-warp partials. Out stored with .cs.
// ---------------------------------------------------------------------------
#define ROWS_PER_BLOCK 4
#define THREADS_B (ROWS_PER_BLOCK * 32)

__global__ __launch_bounds__(THREADS_B) void gather_rows(
    const int* __restrict__ ids,         // [ROWS, 50] int32
    const float* __restrict__ bias,      // [128] fp32
    float* __restrict__ out)             // [ROWS, 128] fp32
{
    __shared__ int s_ids[ROWS_PER_BLOCK][K_ITEMS];

    const int tid  = threadIdx.x;
    const int lane = tid & 31;
    const int wrow = tid >> 5;
    const int row0 = blockIdx.x * ROWS_PER_BLOCK;
    const int sub  = lane & 15;          // lane within half-warp
    const int half = lane >> 4;          // which id of the pair

    const int* gids = ids + (size_t)row0 * K_ITEMS;
    #pragma unroll
    for (int i = tid; i < ROWS_PER_BLOCK * K_ITEMS; i += THREADS_B) {
        s_ids[i / K_ITEMS][i % K_ITEMS] = gids[i];
    }
    __syncthreads();

    const __half2 z = __float2half2_rn(0.f);
    __half2 e0 = z, e1 = z, e2 = z, e3 = z;   // even iterations
    __half2 o0 = z, o1 = z, o2 = z, o3 = z;   // odd iterations

    #pragma unroll
    for (int k = 0; k < K_ITEMS / 2; k++) {   // 25 iterations
        const int v = s_ids[wrow][2 * k + half];
        const int4 r = __ldg((const int4*)(g_WT + (size_t)v * EMBED) + sub);
        const __half2 x0 = *reinterpret_cast<const __half2*>(&r.x);
        const __half2 x1 = *reinterpret_cast<const __half2*>(&r.y);
        const __half2 x2 = *reinterpret_cast<const __half2*>(&r.z);
        const __half2 x3 = *reinterpret_cast<const __half2*>(&r.w);
        if (k & 1) {
            o0 = __hadd2(o0, x0); o1 = __hadd2(o1, x1);
            o2 = __hadd2(o2, x2); o3 = __hadd2(o3, x3);
        } else {
            e0 = __hadd2(e0, x0); e1 = __hadd2(e1, x1);
            e2 = __hadd2(e2, x2); e3 = __hadd2(e3, x3);
        }
    }

    // Single fp32 conversion: combine even/odd sets in fp32.
    float a0, a1, a2, a3, a4, a5, a6, a7;
    {
        const float2 fe0 = __half22float2(e0), fo0 = __half22float2(o0);
        const float2 fe1 = __half22float2(e1), fo1 = __half22float2(o1);
        const float2 fe2 = __half22float2(e2), fo2 = __half22float2(o2);
        const float2 fe3 = __half22float2(e3), fo3 = __half22float2(o3);
        a0 = fe0.x + fo0.x; a1 = fe0.y + fo0.y;
        a2 = fe1.x + fo1.x; a3 = fe1.y + fo1.y;
        a4 = fe2.x + fo2.x; a5 = fe2.y + fo2.y;
        a6 = fe3.x + fo3.x; a7 = fe3.y + fo3.y;
    }

    // Merge the two half-warp partial sums (each covered different ids).
    a0 += __shfl_xor_sync(0xffffffffu, a0, 16);
    a1 += __shfl_xor_sync(0xffffffffu, a1, 16);
    a2 += __shfl_xor_sync(0xffffffffu, a2, 16);
    a3 += __shfl_xor_sync(0xffffffffu, a3, 16);
    a4 += __shfl_xor_sync(0xffffffffu, a4, 16);
    a5 += __shfl_xor_sync(0xffffffffu, a5, 16);
    a6 += __shfl_xor_sync(0xffffffffu, a6, 16);
    a7 += __shfl_xor_sync(0xffffffffu, a7, 16);

    // Lane writes float4 slot j = 2*sub + half (dims 8*sub + 4*half ..+3).
    const int j = 2 * sub + half;
    float4 o = (half == 0) ? make_float4(a0, a1, a2, a3)
                           : make_float4(a4, a5, a6, a7);
    const float4 bv = __ldg((const float4*)bias + j);
    o.x += bv.x; o.y += bv.y; o.z += bv.z; o.w += bv.w;
    __stcs((float4*)(out + (size_t)(row0 + wrow) * EMBED) + j, o);
}

// ---------------------------------------------------------------------------
// Entry point. Inputs (metadata order): content_input int32, W f32, b f32.
// ---------------------------------------------------------------------------
extern "C" void kernel_launch(void* const* d_in, const int* in_sizes, int n_in,
                              void* d_out, int out_size) {
    const int*   ids = (const int*)d_in[0];
    const float* W   = (const float*)d_in[1];
    const float* b   = (const float*)d_in[2];
    float*       out = (float*)d_out;

    dim3 tgrid(VOCAB / VT, EMBED / ET);   // 625 x 4
    transpose_W<<<tgrid, 256>>>((const float4*)W);

    gather_rows<<<ROWS / ROWS_PER_BLOCK, THREADS_B>>>(ids, b, out);
}